// round 15
// baseline (speedup 1.0000x reference)
#include <cuda_runtime.h>
#include <cuda_fp16.h>
#include <math.h>
#include <cstdint>

#define NB 8
#define COUT 64
#define HOUT 63

// ---- scratch (device globals, zero-initialized; no cudaMalloc) ----
// XA2: [b][ks 6][m 1072][qc 4] -> uint2 = (hA, hB) fp16x2; kpA=ks*8+qc, kpB=kpA+4
__device__ __align__(16) uint2 g_XA2[NB * 6 * 1072 * 4];
// WB4: [pl 9][ks 6][jnp 4][lane 32] -> uint4 = (b0_e, b1_e, b0_o, b1_o) for jn=2*jnp{,+1}
__device__ __align__(16) uint4 g_WB4[9 * 6 * 4 * 32];

// classes: 0=oo(4 planes) 1=oe(2) 2=eo(2) 3=ee(1); plane id kh*3+kw
__constant__ int c_dlt[4][4] = {{33,32,1,0},{32,0,0,0},{1,0,0,0},{0,0,0,0}};
__constant__ int c_pl[4][4]  = {{0,2,6,8},{1,7,0,0},{3,5,0,0},{4,0,0,0}};
__constant__ int c_oh[4] = {1, 1, 0, 0};
__constant__ int c_ow[4] = {1, 0, 1, 0};

__device__ __forceinline__ uint32_t pack_h2(float f0, float f1) {
    __half h0 = __float2half_rn(f0);
    __half h1 = __float2half_rn(f1);
    return (uint32_t)__half_as_ushort(h0) | ((uint32_t)__half_as_ushort(h1) << 16);
}

// ================= prep (+wc) single launch =================
__global__ void __launch_bounds__(128)
prep_kernel(const float* __restrict__ x, const float* __restrict__ w) {
    if (blockIdx.x < 512) {
        __shared__ float sm[3][32][17];
        const int b    = blockIdx.x >> 6;
        const int mb16 = blockIdx.x & 63;
        const int tid  = threadIdx.x;
        const int ci = tid >> 2;
        const int mg = tid & 3;

        const float4* p = (const float4*)x + ((size_t)(b * 32 + ci) * 16) * 256 + mb16 * 4 + mg;
        float4 v = p[0];
        float4 s = v, d0 = v, d15 = v;
#pragma unroll
        for (int d = 1; d < 16; d++) {
            float4 u = p[d * 256];
            s.x += u.x; s.y += u.y; s.z += u.z; s.w += u.w;
            if (d == 15) d15 = u;
        }
        const int mo = mg * 4;
        sm[0][ci][mo + 0] = s.x;   sm[0][ci][mo + 1] = s.y;
        sm[0][ci][mo + 2] = s.z;   sm[0][ci][mo + 3] = s.w;
        sm[1][ci][mo + 0] = d0.x;  sm[1][ci][mo + 1] = d0.y;
        sm[1][ci][mo + 2] = d0.z;  sm[1][ci][mo + 3] = d0.w;
        sm[2][ci][mo + 0] = d15.x; sm[2][ci][mo + 1] = d15.y;
        sm[2][ci][mo + 2] = d15.z; sm[2][ci][mo + 3] = d15.w;
        __syncthreads();

#pragma unroll
        for (int it = 0; it < 3; it++) {
            int i = tid + it * 128;
            int qc  = i & 3;
            int ks  = (i >> 2) % 6;
            int row = i / 24;
            int kpA = ks * 8 + qc;
            int kpB = kpA + 4;
            int spA = kpA >> 4, cA = (2 * kpA) & 31;
            int spB = kpB >> 4, cB = (2 * kpB) & 31;
            uint32_t hA = pack_h2(sm[spA][cA][row], sm[spA][cA + 1][row]);
            uint32_t hB = pack_h2(sm[spB][cB][row], sm[spB][cB + 1][row]);
            size_t idx = (((size_t)b * 6 + ks) * 1072 + mb16 * 16 + row) * 4 + qc;
            g_XA2[idx] = make_uint2(hA, hB);
        }
    } else {
        int i = (blockIdx.x - 512) * 128 + threadIdx.x;
        if (i >= 9 * 6 * 4 * 32) return;
        int lane = i & 31;
        int jnp  = (i >> 5) & 3;
        int ks   = (i / 128) % 6;
        int pl   = i / 768;
        int qr = lane >> 2, qc = lane & 3;
        int kh = pl / 3, kw = pl % 3;
        uint32_t pk[4];
#pragma unroll
        for (int jj = 0; jj < 2; jj++) {
            int n = (jnp * 2 + jj) * 8 + qr;
            float f[4];
#pragma unroll
            for (int j = 0; j < 4; j++) {
                int kp  = ks * 8 + qc + (j >> 1) * 4;
                int c96 = 2 * kp + (j & 1);
                int sidx = c96 >> 5, ci = c96 & 31;
                int base = (ci * 64 + n) * 27 + kh * 3 + kw;
                float v;
                if (sidx == 0)      v = w[base] + w[base + 9] + w[base + 18];
                else if (sidx == 1) v = -w[base];
                else                v = -w[base + 18];
                f[j] = v;
            }
            pk[jj * 2]     = pack_h2(f[0], f[1]);
            pk[jj * 2 + 1] = pack_h2(f[2], f[3]);
        }
        g_WB4[i] = make_uint4(pk[0], pk[1], pk[2], pk[3]);
    }
}

// ================= HMMA GEMM + all-warp fused epilogue =================
__device__ __forceinline__ void mma16816(float* d,
                                         uint32_t a0, uint32_t a1, uint32_t a2, uint32_t a3,
                                         uint32_t b0, uint32_t b1) {
    asm volatile(
        "mma.sync.aligned.m16n8k16.row.col.f32.f16.f16.f32 "
        "{%0,%1,%2,%3},{%4,%5,%6,%7},{%8,%9},{%0,%1,%2,%3};"
        : "+f"(d[0]), "+f"(d[1]), "+f"(d[2]), "+f"(d[3])
        : "r"(a0), "r"(a1), "r"(a2), "r"(a3), "r"(b0), "r"(b1));
}

__device__ __forceinline__ void run_plane6(float acc[8][4],
                                           const uint2* __restrict__ Ap,
                                           const uint4* __restrict__ Bp) {
    uint2 av0 = Ap[0];
    uint2 av1 = Ap[32];
    uint4 bb0 = Bp[0], bb1 = Bp[32], bb2 = Bp[64], bb3 = Bp[96];
#pragma unroll
    for (int ks = 0; ks < 6; ks++) {
        uint2 nv0, nv1;
        uint4 nb0, nb1, nb2, nb3;
        if (ks + 1 < 6) {
            Ap += 1072 * 4;
            Bp += 128;
            nv0 = Ap[0];
            nv1 = Ap[32];
            nb0 = Bp[0]; nb1 = Bp[32]; nb2 = Bp[64]; nb3 = Bp[96];
        }
        mma16816(acc[0], av0.x, av1.x, av0.y, av1.y, bb0.x, bb0.y);
        mma16816(acc[1], av0.x, av1.x, av0.y, av1.y, bb0.z, bb0.w);
        mma16816(acc[2], av0.x, av1.x, av0.y, av1.y, bb1.x, bb1.y);
        mma16816(acc[3], av0.x, av1.x, av0.y, av1.y, bb1.z, bb1.w);
        mma16816(acc[4], av0.x, av1.x, av0.y, av1.y, bb2.x, bb2.y);
        mma16816(acc[5], av0.x, av1.x, av0.y, av1.y, bb2.z, bb2.w);
        mma16816(acc[6], av0.x, av1.x, av0.y, av1.y, bb3.x, bb3.y);
        mma16816(acc[7], av0.x, av1.x, av0.y, av1.y, bb3.z, bb3.w);
        av0 = nv0; av1 = nv1;
        bb0 = nb0; bb1 = nb1; bb2 = nb2; bb3 = nb3;
    }
}

// Per-class block body. NMW m-warps x NKG k-groups; ALL 8 warps run the epilogue.
template <int CLS, int NMW, int NKG>
__device__ __forceinline__ void do_block(
    int b, int mbase, float red[8][32][36], float* scb, float* __restrict__ out,
    int w, int lane)
{
    const int wm  = w & (NMW - 1);
    const int grp = w / NMW;
    const int mw  = mbase + wm * 16;
    const int qr = lane >> 2;
    const int qc = lane & 3;

    float acc[8][4];
#pragma unroll
    for (int j = 0; j < 8; j++)
#pragma unroll
        for (int t = 0; t < 4; t++) acc[j][t] = 0.f;

    const int a_lane = (mw + qr) * 4 + qc;
    run_plane6(acc,
               g_XA2 + ((size_t)(b * 6) * 1072 + c_dlt[CLS][grp]) * 4 + a_lane,
               g_WB4 + (size_t)c_pl[CLS][grp] * 768 + lane);

    // park partials (all warps)
#pragma unroll
    for (int jn = 0; jn < 8; jn += 2) {
        *(float4*)&red[w][lane][jn * 4]     = *(float4*)&acc[jn][0];
        *(float4*)&red[w][lane][jn * 4 + 4] = *(float4*)&acc[jn + 1][0];
    }
    __syncthreads();

    // ---- all-warp epilogue ----
    constexpr int ROWS = NMW * 16;
    constexpr int RPW  = ROWS / 8;      // rows per warp
    constexpr int LPR  = 32 / RPW;      // lanes per row
    constexpr int CPL  = 64 / LPR;      // channels per lane

    const int rl   = w * RPW + lane / LPR;       // row_local in block
    const int ch0  = (lane % LPR) * CPL;
    const int wm2  = rl >> 4;
    const int r    = rl & 15;
    const int qr2  = r & 7;
    const int hi8  = r >> 3;

    const float inv_d = 1.0f / 31.0f;
    float v[CPL];
#pragma unroll
    for (int j = 0; j < CPL; j++) {
        const int ch = ch0 + j;
        const int jn = ch >> 3, qc2 = (ch & 7) >> 1, t = ch & 1;
        float s = 0.f;
#pragma unroll
        for (int g = 0; g < NKG; g++)
            s += red[g * NMW + wm2][qr2 * 4 + qc2][jn * 4 + hi8 * 2 + t];
        v[j] = s * inv_d + scb[ch];
    }

    float mx = -INFINITY;
#pragma unroll
    for (int j = 0; j < CPL; j++) mx = fmaxf(mx, v[j]);
#pragma unroll
    for (int o = 1; o < LPR; o <<= 1)
        mx = fmaxf(mx, __shfl_xor_sync(0xffffffffu, mx, o));
    float sum = 0.f;
#pragma unroll
    for (int j = 0; j < CPL; j++) {
        v[j] = __expf(v[j] - mx);
        sum += v[j];
    }
#pragma unroll
    for (int o = 1; o < LPR; o <<= 1)
        sum += __shfl_xor_sync(0xffffffffu, sum, o);
    const float rs = 1.0f / sum;

    const int m  = mbase + wm2 * 16 + qr2 + hi8 * 8;
    const int ho = 2 * (m >> 5) + c_oh[CLS];
    const int wo = 2 * (m & 31) + c_ow[CLS];
    if (ho < HOUT && wo < HOUT) {
        float* op = out + (size_t)b * COUT * (HOUT * HOUT)
                        + (size_t)ho * HOUT + wo + (size_t)ch0 * (HOUT * HOUT);
#pragma unroll
        for (int j = 0; j < CPL; j++) {
            float s = v[j] * rs;
            op[(size_t)j * (HOUT * HOUT)] =
                __fdividef(4.0f, 1.0f + __expf(-2.0f * s)) - 2.0f;   // 2*tanh(s)
        }
    }
}

// grid 576: [0,256) cls0 (32m, 2x4), [256,384) cls1 (64m, 4x2),
//           [384,512) cls2 (64m, 4x2), [512,576) cls3 (128m, 8x1)
__global__ void __launch_bounds__(256, 4)
mma_fused(const float* __restrict__ conv_bias,
          const float* __restrict__ bias,
          float* __restrict__ out) {
    __shared__ float scb[COUT];
    __shared__ float red[8][32][36];

    const int tid  = threadIdx.x;
    const int w    = tid >> 5;
    const int lane = tid & 31;
    if (tid < COUT) scb[tid] = conv_bias[tid] + bias[tid];

    const int bid = blockIdx.x;
    if (bid < 256) {
        do_block<0, 2, 4>(bid >> 5, (bid & 31) * 32, red, scb, out, w, lane);
    } else if (bid < 384) {
        do_block<1, 4, 2>((bid - 256) >> 4, ((bid - 256) & 15) * 64, red, scb, out, w, lane);
    } else if (bid < 512) {
        do_block<2, 4, 2>((bid - 384) >> 4, ((bid - 384) & 15) * 64, red, scb, out, w, lane);
    } else {
        do_block<3, 8, 1>((bid - 512) >> 3, ((bid - 512) & 7) * 128, red, scb, out, w, lane);
    }
}

extern "C" void kernel_launch(void* const* d_in, const int* in_sizes, int n_in,
                              void* d_out, int out_size) {
    (void)in_sizes; (void)n_in; (void)out_size;
    const float* x         = (const float*)d_in[0];
    const float* w         = (const float*)d_in[1];
    const float* conv_bias = (const float*)d_in[2];
    const float* bias      = (const float*)d_in[3];
    float* out             = (float*)d_out;

    prep_kernel<<<566, 128>>>(x, w);
    mma_fused<<<576, 256>>>(conv_bias, bias, out);
}

// round 16
// speedup vs baseline: 1.2424x; 1.2424x over previous
#include <cuda_runtime.h>
#include <cuda_fp16.h>
#include <math.h>
#include <cstdint>

#define NB 8
#define COUT 64
#define HOUT 63

// ---- scratch (device globals, zero-initialized; no cudaMalloc) ----
// XA2: [b][ks 6][m 1072][qc 4] -> uint2 = (hA, hB) fp16x2; kpA=ks*8+qc, kpB=kpA+4
__device__ __align__(16) uint2 g_XA2[NB * 6 * 1072 * 4];
// WB4: [pl 9][ks 6][jnp 4][lane 32] -> uint4 = (b0_e, b1_e, b0_o, b1_o) for jn=2*jnp{,+1}
__device__ __align__(16) uint4 g_WB4[9 * 6 * 4 * 32];

// classes: 0=oo(4 planes) 1=oe(2) 2=eo(2) 3=ee(1); plane id kh*3+kw
__constant__ int c_dlt[4][4] = {{33,32,1,0},{32,0,0,0},{1,0,0,0},{0,0,0,0}};
__constant__ int c_pl[4][4]  = {{0,2,6,8},{1,7,0,0},{3,5,0,0},{4,0,0,0}};
__constant__ int c_oh[4] = {1, 1, 0, 0};
__constant__ int c_ow[4] = {1, 0, 1, 0};

__device__ __forceinline__ uint32_t pack_h2(float f0, float f1) {
    __half h0 = __float2half_rn(f0);
    __half h1 = __float2half_rn(f1);
    return (uint32_t)__half_as_ushort(h0) | ((uint32_t)__half_as_ushort(h1) << 16);
}

// ================= prep (+wc) single launch =================
__global__ void __launch_bounds__(128)
prep_kernel(const float* __restrict__ x, const float* __restrict__ w) {
    if (blockIdx.x < 512) {
        __shared__ float sm[3][32][17];
        const int b    = blockIdx.x >> 6;
        const int mb16 = blockIdx.x & 63;
        const int tid  = threadIdx.x;
        const int ci = tid >> 2;
        const int mg = tid & 3;

        const float4* p = (const float4*)x + ((size_t)(b * 32 + ci) * 16) * 256 + mb16 * 4 + mg;
        float4 v = p[0];
        float4 s = v, d0 = v, d15 = v;
#pragma unroll
        for (int d = 1; d < 16; d++) {
            float4 u = p[d * 256];
            s.x += u.x; s.y += u.y; s.z += u.z; s.w += u.w;
            if (d == 15) d15 = u;
        }
        const int mo = mg * 4;
        sm[0][ci][mo + 0] = s.x;   sm[0][ci][mo + 1] = s.y;
        sm[0][ci][mo + 2] = s.z;   sm[0][ci][mo + 3] = s.w;
        sm[1][ci][mo + 0] = d0.x;  sm[1][ci][mo + 1] = d0.y;
        sm[1][ci][mo + 2] = d0.z;  sm[1][ci][mo + 3] = d0.w;
        sm[2][ci][mo + 0] = d15.x; sm[2][ci][mo + 1] = d15.y;
        sm[2][ci][mo + 2] = d15.z; sm[2][ci][mo + 3] = d15.w;
        __syncthreads();

#pragma unroll
        for (int it = 0; it < 3; it++) {
            int i = tid + it * 128;
            int qc  = i & 3;
            int ks  = (i >> 2) % 6;
            int row = i / 24;
            int kpA = ks * 8 + qc;
            int kpB = kpA + 4;
            int spA = kpA >> 4, cA = (2 * kpA) & 31;
            int spB = kpB >> 4, cB = (2 * kpB) & 31;
            uint32_t hA = pack_h2(sm[spA][cA][row], sm[spA][cA + 1][row]);
            uint32_t hB = pack_h2(sm[spB][cB][row], sm[spB][cB + 1][row]);
            size_t idx = (((size_t)b * 6 + ks) * 1072 + mb16 * 16 + row) * 4 + qc;
            g_XA2[idx] = make_uint2(hA, hB);
        }
    } else {
        int i = (blockIdx.x - 512) * 128 + threadIdx.x;
        if (i >= 9 * 6 * 4 * 32) return;
        int lane = i & 31;
        int jnp  = (i >> 5) & 3;
        int ks   = (i / 128) % 6;
        int pl   = i / 768;
        int qr = lane >> 2, qc = lane & 3;
        int kh = pl / 3, kw = pl % 3;
        uint32_t pk[4];
#pragma unroll
        for (int jj = 0; jj < 2; jj++) {
            int n = (jnp * 2 + jj) * 8 + qr;
            float f[4];
#pragma unroll
            for (int j = 0; j < 4; j++) {
                int kp  = ks * 8 + qc + (j >> 1) * 4;
                int c96 = 2 * kp + (j & 1);
                int sidx = c96 >> 5, ci = c96 & 31;
                int base = (ci * 64 + n) * 27 + kh * 3 + kw;
                float v;
                if (sidx == 0)      v = w[base] + w[base + 9] + w[base + 18];
                else if (sidx == 1) v = -w[base];
                else                v = -w[base + 18];
                f[j] = v;
            }
            pk[jj * 2]     = pack_h2(f[0], f[1]);
            pk[jj * 2 + 1] = pack_h2(f[2], f[3]);
        }
        g_WB4[i] = make_uint4(pk[0], pk[1], pk[2], pk[3]);
    }
}

// ================= HMMA GEMM (f16 accumulate) + fused epilogue =================
__device__ __forceinline__ void mma16816h(uint32_t& d0, uint32_t& d1,
                                          uint32_t a0, uint32_t a1, uint32_t a2, uint32_t a3,
                                          uint32_t b0, uint32_t b1) {
    asm volatile(
        "mma.sync.aligned.m16n8k16.row.col.f16.f16.f16.f16 "
        "{%0,%1},{%2,%3,%4,%5},{%6,%7},{%0,%1};"
        : "+r"(d0), "+r"(d1)
        : "r"(a0), "r"(a1), "r"(a2), "r"(a3), "r"(b0), "r"(b1));
}

// One kh/kw plane (6 ksteps), fully unrolled with 1-deep register pipeline.
__device__ __forceinline__ void run_plane6(uint32_t acc[8][2],
                                           const uint2* __restrict__ Ap,
                                           const uint4* __restrict__ Bp) {
    uint2 av0 = Ap[0];
    uint2 av1 = Ap[32];
    uint4 bb0 = Bp[0], bb1 = Bp[32], bb2 = Bp[64], bb3 = Bp[96];
#pragma unroll
    for (int ks = 0; ks < 6; ks++) {
        uint2 nv0, nv1;
        uint4 nb0, nb1, nb2, nb3;
        if (ks + 1 < 6) {
            Ap += 1072 * 4;
            Bp += 128;
            nv0 = Ap[0];
            nv1 = Ap[32];
            nb0 = Bp[0]; nb1 = Bp[32]; nb2 = Bp[64]; nb3 = Bp[96];
        }
        mma16816h(acc[0][0], acc[0][1], av0.x, av1.x, av0.y, av1.y, bb0.x, bb0.y);
        mma16816h(acc[1][0], acc[1][1], av0.x, av1.x, av0.y, av1.y, bb0.z, bb0.w);
        mma16816h(acc[2][0], acc[2][1], av0.x, av1.x, av0.y, av1.y, bb1.x, bb1.y);
        mma16816h(acc[3][0], acc[3][1], av0.x, av1.x, av0.y, av1.y, bb1.z, bb1.w);
        mma16816h(acc[4][0], acc[4][1], av0.x, av1.x, av0.y, av1.y, bb2.x, bb2.y);
        mma16816h(acc[5][0], acc[5][1], av0.x, av1.x, av0.y, av1.y, bb2.z, bb2.w);
        mma16816h(acc[6][0], acc[6][1], av0.x, av1.x, av0.y, av1.y, bb3.x, bb3.y);
        mma16816h(acc[7][0], acc[7][1], av0.x, av1.x, av0.y, av1.y, bb3.z, bb3.w);
        av0 = nv0; av1 = nv1;
        bb0 = nb0; bb1 = nb1; bb2 = nb2; bb3 = nb3;
    }
}

// grid 576, every block = 6 k-iters/warp (single balanced wave):
//   [0,256):   cls0, 32m tiles, 2 m-warps x 4 k-groups
//   [256,384): cls1, 64m tiles, 4 m-warps x 2 k-groups
//   [384,512): cls2, 64m tiles, 4 m-warps x 2 k-groups
//   [512,576): cls3, 128m tiles, 8 m-warps x 1 k-group
__global__ void __launch_bounds__(256, 4)
mma_fused(const float* __restrict__ conv_bias,
          const float* __restrict__ bias,
          float* __restrict__ out) {
    __shared__ float scb[COUT];
    __shared__ float red[6][32][36];

    const int tid  = threadIdx.x;
    const int w    = tid >> 5;
    const int lane = tid & 31;
    if (tid < COUT) scb[tid] = conv_bias[tid] + bias[tid];

    const int bid = blockIdx.x;
    int cls, b, mbase, lgNMW;
    if (bid < 256)      { cls = 0; b = bid >> 5;         mbase = (bid & 31) * 32;          lgNMW = 1; }
    else if (bid < 384) { cls = 1; b = (bid - 256) >> 4; mbase = ((bid - 256) & 15) * 64;  lgNMW = 2; }
    else if (bid < 512) { cls = 2; b = (bid - 384) >> 4; mbase = ((bid - 384) & 15) * 64;  lgNMW = 2; }
    else                { cls = 3; b = (bid - 512) >> 3; mbase = ((bid - 512) & 7) * 128;  lgNMW = 3; }
    const int NMW = 1 << lgNMW;
    const int NKG = 8 >> lgNMW;
    const int wm  = w & (NMW - 1);
    const int grp = w >> lgNMW;
    const int mw  = mbase + wm * 16;
    const int qr = lane >> 2;
    const int qc = lane & 3;

    uint32_t acch[8][2];
#pragma unroll
    for (int j = 0; j < 8; j++) { acch[j][0] = 0u; acch[j][1] = 0u; }

    const int a_lane = (mw + qr) * 4 + qc;

    run_plane6(acch,
               g_XA2 + ((size_t)(b * 6) * 1072 + c_dlt[cls][grp]) * 4 + a_lane,
               g_WB4 + (size_t)c_pl[cls][grp] * 768 + lane);

    // unpack f16 partials -> f32 (cross-group sums done in f32)
    float acc[8][4];
#pragma unroll
    for (int j = 0; j < 8; j++) {
        float2 lo = __half22float2(*(__half2*)&acch[j][0]);
        float2 hi = __half22float2(*(__half2*)&acch[j][1]);
        acc[j][0] = lo.x; acc[j][1] = lo.y;
        acc[j][2] = hi.x; acc[j][3] = hi.y;
    }

    // ---- cross-group reduction ----
    if (grp > 0) {
        const int ri = (grp - 1) * NMW + wm;
#pragma unroll
        for (int jn = 0; jn < 8; jn += 2) {
            *(float4*)&red[ri][lane][jn * 4]     = *(float4*)&acc[jn][0];
            *(float4*)&red[ri][lane][jn * 4 + 4] = *(float4*)&acc[jn + 1][0];
        }
    }
    __syncthreads();
    if (grp > 0) return;

    for (int g = 1; g < NKG; g++) {
        const int ri = (g - 1) * NMW + wm;
#pragma unroll
        for (int jn = 0; jn < 8; jn++) {
#pragma unroll
            for (int t = 0; t < 4; t++) acc[jn][t] += red[ri][lane][jn * 4 + t];
        }
    }

    // ---- fused epilogue: mean-scale + biases + softmax + 2*tanh ----
    const float inv_d = 1.0f / 31.0f;
    float mx0 = -INFINITY, mx1 = -INFINITY;
#pragma unroll
    for (int jn = 0; jn < 8; jn++) {
#pragma unroll
        for (int t = 0; t < 2; t++) {
            float c = scb[jn * 8 + 2 * qc + t];
            acc[jn][t]     = acc[jn][t]     * inv_d + c;
            acc[jn][2 + t] = acc[jn][2 + t] * inv_d + c;
            mx0 = fmaxf(mx0, acc[jn][t]);
            mx1 = fmaxf(mx1, acc[jn][2 + t]);
        }
    }
    mx0 = fmaxf(mx0, __shfl_xor_sync(0xffffffffu, mx0, 1));
    mx0 = fmaxf(mx0, __shfl_xor_sync(0xffffffffu, mx0, 2));
    mx1 = fmaxf(mx1, __shfl_xor_sync(0xffffffffu, mx1, 1));
    mx1 = fmaxf(mx1, __shfl_xor_sync(0xffffffffu, mx1, 2));

    float s0 = 0.f, s1 = 0.f;
#pragma unroll
    for (int jn = 0; jn < 8; jn++) {
#pragma unroll
        for (int t = 0; t < 2; t++) {
            acc[jn][t]     = __expf(acc[jn][t] - mx0);
            acc[jn][2 + t] = __expf(acc[jn][2 + t] - mx1);
            s0 += acc[jn][t];
            s1 += acc[jn][2 + t];
        }
    }
    s0 += __shfl_xor_sync(0xffffffffu, s0, 1);
    s0 += __shfl_xor_sync(0xffffffffu, s0, 2);
    s1 += __shfl_xor_sync(0xffffffffu, s1, 1);
    s1 += __shfl_xor_sync(0xffffffffu, s1, 2);
    const float rs0 = 1.0f / s0;
    const float rs1 = 1.0f / s1;

    const int oh = c_oh[cls], ow = c_ow[cls];
    const int m0 = mw + qr;
    const int hq = m0 >> 5;
    const int wq0 = m0 & 31;
    const int ho = 2 * hq + oh;
    const int wo0 = 2 * wq0 + ow;
    const int wo1 = 2 * (wq0 + 8) + ow;
    float* obase = out + (size_t)b * COUT * (HOUT * HOUT) + (size_t)ho * HOUT;

    if (ho < HOUT) {
        const bool v0 = (wo0 < HOUT);
        const bool v1 = (wo1 < HOUT);
#pragma unroll
        for (int jn = 0; jn < 8; jn++) {
#pragma unroll
            for (int t = 0; t < 2; t++) {
                int ch = jn * 8 + 2 * qc + t;
                float* op = obase + (size_t)ch * (HOUT * HOUT);
                if (v0) {
                    float s = acc[jn][t] * rs0;
                    op[wo0] = __fdividef(4.0f, 1.0f + __expf(-2.0f * s)) - 2.0f;  // 2*tanh
                }
                if (v1) {
                    float s = acc[jn][2 + t] * rs1;
                    op[wo1] = __fdividef(4.0f, 1.0f + __expf(-2.0f * s)) - 2.0f;
                }
            }
        }
    }
}

extern "C" void kernel_launch(void* const* d_in, const int* in_sizes, int n_in,
                              void* d_out, int out_size) {
    (void)in_sizes; (void)n_in; (void)out_size;
    const float* x         = (const float*)d_in[0];
    const float* w         = (const float*)d_in[1];
    const float* conv_bias = (const float*)d_in[2];
    const float* bias      = (const float*)d_in[3];
    float* out             = (float*)d_out;

    prep_kernel<<<566, 128>>>(x, w);
    mma_fused<<<576, 256>>>(conv_bias, bias, out);
}